// round 11
// baseline (speedup 1.0000x reference)
#include <cuda_runtime.h>
#include <cuda_fp16.h>
#include <math.h>
#include <stdint.h>

#define BB 8
#define SS 4096
#define HH 768
#define MS 64
#define F1 4096
#define F2 256
#define SEPTOK 2
#define MROWS 512          // BB*MS
#define NSPLIT 16
#define PSPLIT 4           // token-axis split for pooling

// ---------------- scratch (device globals; no allocation allowed) ----------
// 1024B alignment is load-bearing: cp.async.cg 16B requires 16B-aligned
// global addresses; vector stores require 4/8/16B.
__device__ __align__(1024) __half g_sentb[MROWS * HH];    // A GEMM1, fp16
__device__ __align__(1024) __half g_w1b[F1 * HH];         // B GEMM1: W1^T fp16
__device__ __align__(1024) __half g_x1b[MROWS * F1];      // A GEMM2, fp16
__device__ __align__(1024) __half g_w2b[F2 * F1];         // B GEMM2: W2^T fp16
__device__ __align__(1024) float g_x2p[NSPLIT * MROWS * F2];   // GEMM2 split-K partials
__device__ __align__(1024) float g_poolp[PSPLIT * MROWS * HH]; // pooling partial sums
__device__ int   g_sep_pos[BB][SS];
__device__ int   g_nsep[BB];

__device__ __forceinline__ float gelu_exact(float x) {
    return 0.5f * x * (1.0f + erff(x * 0.70710678118654752f));
}

__device__ __forceinline__ uint32_t smem_u32(const void* p) {
    uint32_t a;
    asm("{ .reg .u64 t; cvta.to.shared.u64 t, %1; cvt.u32.u64 %0, t; }" : "=r"(a) : "l"(p));
    return a;
}
__device__ __forceinline__ uint32_t sw128(uint32_t off) {
    return off ^ ((off >> 3) & 0x70);
}
__device__ __forceinline__ void cp_async16(uint32_t dst, const void* src) {
    asm volatile("cp.async.cg.shared.global [%0], [%1], 16;" :: "r"(dst), "l"(src) : "memory");
}
__device__ __forceinline__ void cp_commit() {
    asm volatile("cp.async.commit_group;" ::: "memory");
}
template<int N>
__device__ __forceinline__ void cp_waitg() {
    asm volatile("cp.async.wait_group %0;" :: "n"(N) : "memory");
}
__device__ __forceinline__ void ldsm_x4(uint32_t* r, uint32_t addr) {
    asm volatile("ldmatrix.sync.aligned.m8n8.x4.shared.b16 {%0,%1,%2,%3}, [%4];"
                 : "=r"(r[0]), "=r"(r[1]), "=r"(r[2]), "=r"(r[3]) : "r"(addr));
}
__device__ __forceinline__ void mma16816(float* d, const uint32_t* a, const uint32_t* b) {
    asm volatile(
        "mma.sync.aligned.m16n8k16.row.col.f32.f16.f16.f32 "
        "{%0,%1,%2,%3}, {%4,%5,%6,%7}, {%8,%9}, {%0,%1,%2,%3};"
        : "+f"(d[0]), "+f"(d[1]), "+f"(d[2]), "+f"(d[3])
        : "r"(a[0]), "r"(a[1]), "r"(a[2]), "r"(a[3]), "r"(b[0]), "r"(b[1]));
}

// segment bounds shared by pool kernels (reference semantics)
__device__ __forceinline__ void seg_bounds(int b, int s, int& t0, int& t1) {
    const int n = g_nsep[b];
    t0 = 0; t1 = 0;
    if (n == 0) {
        if (s == 0) { t0 = 0; t1 = SS; }
    } else if (s < n) {
        if (s == 0) { t0 = 0; t1 = g_sep_pos[b][0] + 1; }
        else        { t0 = g_sep_pos[b][s - 1] + 1; t1 = g_sep_pos[b][s]; }
    } else if (s == n) {
        t0 = g_sep_pos[b][n - 1] + 1; t1 = SS - 1;
    }
}

// ---------------- 1) sep scan (shuffle block scan) --------------------------
__global__ void sep_scan_kernel(const int* __restrict__ ids32) {
    const int b = blockIdx.x;
    const int tid = threadIdx.x;                  // 256
    const int stride = (ids32[1] == 0) ? 2 : 1;   // int64 vs int32 auto-detect
    const int* row = ids32 + (size_t)b * SS * stride;

    const int base = tid * 16;
    int c = 0;
    #pragma unroll
    for (int i = 0; i < 16; i++)
        if (row[(base + i) * stride] == SEPTOK) c++;

    const int lane = tid & 31, w = tid >> 5;
    int incl = c;
    #pragma unroll
    for (int o = 1; o < 32; o <<= 1) {
        int t = __shfl_up_sync(0xffffffffu, incl, o);
        if (lane >= o) incl += t;
    }
    __shared__ int wsum[8], woff[8];
    if (lane == 31) wsum[w] = incl;
    __syncthreads();
    if (tid == 0) {
        int a = 0;
        #pragma unroll
        for (int i = 0; i < 8; i++) { woff[i] = a; a += wsum[i]; }
        g_nsep[b] = a;
    }
    __syncthreads();

    int off = woff[w] + incl - c;
    for (int i = 0; i < 16; i++)
        if (row[(base + i) * stride] == SEPTOK)
            g_sep_pos[b][off++] = base + i;
}

// ---------------- 2a) pooling partial sums (token-split x4) -----------------
__global__ void pool_partial_kernel(const float* __restrict__ hidden) {
    const int s   = blockIdx.x;   // 0..63
    const int b   = blockIdx.y;   // 0..7
    const int z   = blockIdx.z;   // 0..PSPLIT-1
    const int tid = threadIdx.x;  // 192 (= HH/4)

    int t0, t1;
    seg_bounds(b, s, t0, t1);
    const int len = t1 - t0;
    const int tz0 = t0 + (len * z) / PSPLIT;
    const int tz1 = t0 + (len * (z + 1)) / PSPLIT;

    const float4* hb = (const float4*)(hidden + (size_t)b * SS * HH);
    float4 s0 = make_float4(0.f,0.f,0.f,0.f), s1 = s0, s2 = s0, s3 = s0;
    int t = tz0;
    for (; t + 3 < tz1; t += 4) {
        float4 v0 = hb[(size_t)t * 192 + tid];
        float4 v1 = hb[(size_t)(t + 1) * 192 + tid];
        float4 v2 = hb[(size_t)(t + 2) * 192 + tid];
        float4 v3 = hb[(size_t)(t + 3) * 192 + tid];
        s0.x += v0.x; s0.y += v0.y; s0.z += v0.z; s0.w += v0.w;
        s1.x += v1.x; s1.y += v1.y; s1.z += v1.z; s1.w += v1.w;
        s2.x += v2.x; s2.y += v2.y; s2.z += v2.z; s2.w += v2.w;
        s3.x += v3.x; s3.y += v3.y; s3.z += v3.z; s3.w += v3.w;
    }
    for (; t < tz1; t++) {
        float4 v0 = hb[(size_t)t * 192 + tid];
        s0.x += v0.x; s0.y += v0.y; s0.z += v0.z; s0.w += v0.w;
    }
    float4 r;
    r.x = s0.x + s1.x + s2.x + s3.x;
    r.y = s0.y + s1.y + s2.y + s3.y;
    r.z = s0.z + s1.z + s2.z + s3.z;
    r.w = s0.w + s1.w + s2.w + s3.w;
    ((float4*)g_poolp)[((size_t)z * MROWS + b * MS + s) * 192 + tid] = r;
}

// ---------------- 2b) pooling combine: sum partials, divide, fp16 -----------
__global__ void pool_combine_kernel() {
    const int s   = blockIdx.x;
    const int b   = blockIdx.y;
    const int tid = threadIdx.x;  // 192

    int t0, t1;
    seg_bounds(b, s, t0, t1);
    const int cnt = t1 - t0;
    const float inv = (cnt > 0) ? (1.0f / (float)cnt) : 0.0f;

    const size_t rowi = (size_t)(b * MS + s) * 192 + tid;
    float4 acc = make_float4(0.f, 0.f, 0.f, 0.f);
    #pragma unroll
    for (int z = 0; z < PSPLIT; z++) {
        float4 p = ((const float4*)g_poolp)[(size_t)z * MROWS * 192 + rowi];
        acc.x += p.x; acc.y += p.y; acc.z += p.z; acc.w += p.w;
    }
    const size_t rb = (size_t)(b * MS + s) * HH + tid * 4;
    *(__half2*)(&g_sentb[rb]) =
        __halves2half2(__float2half(acc.x * inv), __float2half(acc.y * inv));
    *(__half2*)(&g_sentb[rb + 2]) =
        __halves2half2(__float2half(acc.z * inv), __float2half(acc.w * inv));
}

// ---------------- 3) weight transpose, fp16 -------------------------------
// W: [K, N] row-major  ->  out: [N, K] fp16
__global__ void conv_w_kernel(const float* __restrict__ W, __half* __restrict__ out,
                              int K, int N) {
    __shared__ float t[32][33];
    const int n0 = blockIdx.x * 32, k0 = blockIdx.y * 32;
    const int tx = threadIdx.x, ty = threadIdx.y;   // 32 x 8
    #pragma unroll
    for (int i = 0; i < 4; i++)
        t[ty + i * 8][tx] = W[(size_t)(k0 + ty + i * 8) * N + n0 + tx];
    __syncthreads();
    #pragma unroll
    for (int i = 0; i < 4; i++) {
        const int nn = n0 + ty + i * 8;
        out[(size_t)nn * K + k0 + tx] = __float2half(t[tx][ty + i * 8]);
    }
}

// ---------------- 4) mma.sync fp16 GEMM, 128x128 tile, K staged 128 ---------
// A: [M, lda] K-major fp16.  B: [N, ldb] K-major fp16 (B^T).
// 3-deep cp.async ring; 8 warps 4(m)x2(n), warp tile 32x64.
// EPI==1: D + bias -> GELU -> fp16 x1.  EPI==0: fp32 split-K partials.
template<int EPI>
__global__ __launch_bounds__(256)
void mma_gemm(const __half* __restrict__ A, int lda,
              const __half* __restrict__ Bm, int ldb,
              int nStages,            // number of 128-wide K stages
              const float* __restrict__ bias,
              float* __restrict__ Cout,
              __half* __restrict__ OutB)
{
    extern __shared__ char dsm_raw[];
    char* dsm = (char*)(((uintptr_t)dsm_raw + 1023) & ~(uintptr_t)1023);

    const int tid  = threadIdx.x;
    const int wid  = tid >> 5, lane = tid & 31;
    const int m0   = blockIdx.y * 128;
    const int n0   = blockIdx.x * 128;
    const int z    = blockIdx.z;
    const int ks0  = z * nStages * 128;

    const uint32_t smBase = smem_u32(dsm);

    auto load_stage = [&](int buf, int s) {
        const int ko = ks0 + s * 128;
        const uint32_t dA = smBase + buf * 32768;
        const uint32_t dB = smBase + 98304 + buf * 32768;
        #pragma unroll
        for (int sub = 0; sub < 2; sub++) {
            const __half* Ag = A  + (size_t)m0 * lda + ko + sub * 64;
            const __half* Bg = Bm + (size_t)n0 * ldb + ko + sub * 64;
            #pragma unroll
            for (int i = 0; i < 4; i++) {
                const int ch = tid + i * 256;     // 1024 16B chunks / sub-tile
                const int r = ch >> 3, c = ch & 7;
                const uint32_t sw = sw128((uint32_t)(r * 128 + c * 16)) + sub * 16384;
                cp_async16(dA + sw, Ag + (size_t)r * lda + c * 8);
                cp_async16(dB + sw, Bg + (size_t)r * ldb + c * 8);
            }
        }
    };

    // ---- warp/lane fragment geometry
    const int wm0 = (wid & 3) * 32;
    const int wn0 = (wid >> 2) * 64;
    const int grp = lane >> 3, rowin = lane & 7;
    const int a_mloc = rowin + ((grp & 1) << 3);
    const int a_koff = (grp >> 1) << 4;
    const int b_nloc = rowin + ((grp >> 1) << 3);
    const int b_koff = (grp & 1) << 4;

    float acc[2][8][4];
    #pragma unroll
    for (int mt = 0; mt < 2; mt++)
        #pragma unroll
        for (int nt = 0; nt < 8; nt++)
            #pragma unroll
            for (int q = 0; q < 4; q++) acc[mt][nt][q] = 0.f;

    load_stage(0, 0);
    cp_commit();
    if (nStages > 1) { load_stage(1, 1); cp_commit(); }

    int buf = 0;
    for (int s = 0; s < nStages; s++) {
        if (s + 1 < nStages) cp_waitg<1>(); else cp_waitg<0>();
        __syncthreads();

        #pragma unroll
        for (int sub = 0; sub < 2; sub++) {
            const uint32_t uA = smBase + buf * 32768 + sub * 16384;
            const uint32_t uB = smBase + 98304 + buf * 32768 + sub * 16384;
            const uint32_t aRow[2] = {
                uA + (uint32_t)((wm0 + a_mloc) * 128),
                uA + (uint32_t)((wm0 + 16 + a_mloc) * 128) };
            const uint32_t aXor = (uint32_t)(((wm0 + a_mloc) & 7) << 4);
            const uint32_t bXor = (uint32_t)(((wn0 + b_nloc) & 7) << 4);

            #pragma unroll
            for (int kk = 0; kk < 4; kk++) {
                uint32_t afr[2][4];
                #pragma unroll
                for (int mt = 0; mt < 2; mt++)
                    ldsm_x4(afr[mt], aRow[mt] + (((uint32_t)(kk * 32 + a_koff)) ^ aXor));

                uint32_t bfr[8][2];
                #pragma unroll
                for (int p = 0; p < 4; p++) {
                    uint32_t r4[4];
                    const uint32_t bRow = uB + (uint32_t)((wn0 + p * 16 + b_nloc) * 128);
                    ldsm_x4(r4, bRow + (((uint32_t)(kk * 32 + b_koff)) ^ bXor));
                    bfr[2 * p][0] = r4[0]; bfr[2 * p][1] = r4[1];
                    bfr[2 * p + 1][0] = r4[2]; bfr[2 * p + 1][1] = r4[3];
                }

                #pragma unroll
                for (int mt = 0; mt < 2; mt++)
                    #pragma unroll
                    for (int nt = 0; nt < 8; nt++)
                        mma16816(acc[mt][nt], afr[mt], bfr[nt]);
            }
        }

        // 3-buffer ring: overwrite target was consumed at stage s-1; the
        // top-of-loop barrier for stage s already fenced all its readers.
        if (s + 2 < nStages) { load_stage((s + 2) % 3, s + 2); cp_commit(); }
        buf = (buf + 1) % 3;
    }

    // ---- epilogue
    #pragma unroll
    for (int mt = 0; mt < 2; mt++) {
        const int rA = m0 + wm0 + mt * 16 + (lane >> 2);
        #pragma unroll
        for (int half = 0; half < 2; half++) {
            const int r = rA + half * 8;
            if (EPI == 1) {
                const size_t rowbase = (size_t)r * F1;
                #pragma unroll
                for (int nt = 0; nt < 8; nt++) {
                    const int f = n0 + wn0 + nt * 8 + (lane & 3) * 2;
                    float v0 = gelu_exact(acc[mt][nt][2 * half]     + __ldg(&bias[f]));
                    float v1 = gelu_exact(acc[mt][nt][2 * half + 1] + __ldg(&bias[f + 1]));
                    *(__half2*)(&OutB[rowbase + f]) =
                        __halves2half2(__float2half(v0), __float2half(v1));
                }
            } else {
                float* Cp = Cout + (size_t)z * MROWS * F2 + (size_t)r * F2;
                #pragma unroll
                for (int nt = 0; nt < 8; nt++) {
                    const int f = n0 + wn0 + nt * 8 + (lane & 3) * 2;
                    float2 v; v.x = acc[mt][nt][2 * half]; v.y = acc[mt][nt][2 * half + 1];
                    *(float2*)(Cp + f) = v;
                }
            }
        }
    }
}

// ---------------- 5) fused split-K reduce + bias + GELU + head --------------
__global__ void reduce_head_kernel(const float* __restrict__ b2,
                                   const float* __restrict__ W3,
                                   const float* __restrict__ b3,
                                   float* __restrict__ out) {
    const int row = blockIdx.x;   // 512
    const int tid = threadIdx.x;  // 256
    const int idx = row * F2 + tid;
    float s = 0.f;
    #pragma unroll
    for (int i = 0; i < NSPLIT; i++) s += g_x2p[(size_t)i * MROWS * F2 + idx];
    const float x = gelu_exact(s + b2[tid]);

    __shared__ float sh0[256];
    __shared__ float sh1[256];
    sh0[tid] = x * W3[tid * 2 + 0];
    sh1[tid] = x * W3[tid * 2 + 1];
    __syncthreads();
    for (int o = 128; o > 0; o >>= 1) {
        if (tid < o) { sh0[tid] += sh0[tid + o]; sh1[tid] += sh1[tid + o]; }
        __syncthreads();
    }
    if (tid == 0) {
        out[row * 2 + 0] = sh0[0] + b3[0];
        out[row * 2 + 1] = sh1[0] + b3[1];
    }
}

// ---------------- launch ----------------------------------------------------
extern "C" void kernel_launch(void* const* d_in, const int* in_sizes, int n_in,
                              void* d_out, int out_size) {
    const float* hidden = (const float*)d_in[0];
    const int*   ids32  = (const int*)  d_in[1];
    const float* W1 = (const float*)d_in[2];
    const float* b1 = (const float*)d_in[3];
    const float* W2 = (const float*)d_in[4];
    const float* b2 = (const float*)d_in[5];
    const float* W3 = (const float*)d_in[6];
    const float* b3 = (const float*)d_in[7];
    float* out = (float*)d_out;

    void *p_sentb, *p_w1b, *p_x1b, *p_w2b, *p_x2p;
    cudaGetSymbolAddress(&p_sentb, g_sentb);
    cudaGetSymbolAddress(&p_w1b,   g_w1b);
    cudaGetSymbolAddress(&p_x1b,   g_x1b);
    cudaGetSymbolAddress(&p_w2b,   g_w2b);
    cudaGetSymbolAddress(&p_x2p,   g_x2p);

    // lazily created host-side objects (no device memory involved); the
    // enqueued work graph is identical on every call.
    static cudaStream_t s1 = nullptr;
    static cudaEvent_t eFork = nullptr, eJoin = nullptr;
    if (s1 == nullptr) {
        cudaStreamCreateWithFlags(&s1, cudaStreamNonBlocking);
        cudaEventCreateWithFlags(&eFork, cudaEventDisableTiming);
        cudaEventCreateWithFlags(&eJoin, cudaEventDisableTiming);
    }

    const int SMEM_DYN = 197632;   // 3 x (32KB A + 32KB B) + 1KB align slack
    cudaFuncSetAttribute(mma_gemm<1>, cudaFuncAttributeMaxDynamicSharedMemorySize, SMEM_DYN);
    cudaFuncSetAttribute(mma_gemm<0>, cudaFuncAttributeMaxDynamicSharedMemorySize, SMEM_DYN);

    // fork: weight conversions run on s1 concurrently with sep+pool
    cudaEventRecord(eFork, 0);
    cudaStreamWaitEvent(s1, eFork, 0);
    conv_w_kernel<<<dim3(F1 / 32, HH / 32), dim3(32, 8), 0, s1>>>(
        W1, (__half*)p_w1b, HH, F1);
    conv_w_kernel<<<dim3(F2 / 32, F1 / 32), dim3(32, 8), 0, s1>>>(
        W2, (__half*)p_w2b, F1, F2);
    cudaEventRecord(eJoin, s1);

    sep_scan_kernel<<<BB, 256>>>(ids32);
    pool_partial_kernel<<<dim3(MS, BB, PSPLIT), 192>>>(hidden);
    pool_combine_kernel<<<dim3(MS, BB), 192>>>();

    // join before GEMM1 (covers GEMM2's W2 dependency as well)
    cudaStreamWaitEvent(0, eJoin, 0);

    // GEMM1: [512, 768] x [4096, 768]^T -> gelu -> fp16 x1  (6 stages)
    mma_gemm<1><<<dim3(F1 / 128, MROWS / 128, 1), 256, SMEM_DYN>>>(
        (const __half*)p_sentb, HH, (const __half*)p_w1b, HH,
        HH / 128, b1, nullptr, (__half*)p_x1b);

    // GEMM2: [512, 4096] x [256, 4096]^T, split-K=16 -> fp32 partials (2 stages)
    mma_gemm<0><<<dim3(F2 / 128, MROWS / 128, NSPLIT), 256, SMEM_DYN>>>(
        (const __half*)p_x1b, F1, (const __half*)p_w2b, F1,
        F1 / (128 * NSPLIT), nullptr, (float*)p_x2p, nullptr);

    reduce_head_kernel<<<MROWS, 256>>>(b2, W3, b3, out);
}

// round 12
// speedup vs baseline: 1.3811x; 1.3811x over previous
#include <cuda_runtime.h>
#include <cuda_fp16.h>
#include <math.h>
#include <stdint.h>

#define BB 8
#define SS 4096
#define HH 768
#define MS 64
#define F1 4096
#define F2 256
#define SEPTOK 2
#define MROWS 512          // BB*MS
#define NSPLIT 16
#define CHUNK_T 16                          // tokens per bulk chunk
#define CHUNK_BYTES (CHUNK_T * HH * 4)      // 49152

// ---------------- scratch (device globals; no allocation allowed) ----------
__device__ __align__(1024) __half g_sentb[MROWS * HH];    // A GEMM1, fp16
__device__ __align__(1024) __half g_w1b[F1 * HH];         // B GEMM1: W1^T fp16
__device__ __align__(1024) __half g_x1b[MROWS * F1];      // A GEMM2, fp16
__device__ __align__(1024) __half g_w2b[F2 * F1];         // B GEMM2: W2^T fp16
__device__ __align__(1024) float g_x2p[NSPLIT * MROWS * F2];   // split-K partials
__device__ int   g_sep_pos[BB][SS];
__device__ int   g_nsep[BB];

__device__ __forceinline__ float gelu_exact(float x) {
    return 0.5f * x * (1.0f + erff(x * 0.70710678118654752f));
}

__device__ __forceinline__ uint32_t smem_u32(const void* p) {
    uint32_t a;
    asm("{ .reg .u64 t; cvta.to.shared.u64 t, %1; cvt.u32.u64 %0, t; }" : "=r"(a) : "l"(p));
    return a;
}
__device__ __forceinline__ uint32_t sw128(uint32_t off) {
    return off ^ ((off >> 3) & 0x70);
}
__device__ __forceinline__ void cp_async16(uint32_t dst, const void* src) {
    asm volatile("cp.async.cg.shared.global [%0], [%1], 16;" :: "r"(dst), "l"(src) : "memory");
}
__device__ __forceinline__ void cp_commit() {
    asm volatile("cp.async.commit_group;" ::: "memory");
}
template<int N>
__device__ __forceinline__ void cp_waitg() {
    asm volatile("cp.async.wait_group %0;" :: "n"(N) : "memory");
}
__device__ __forceinline__ void ldsm_x4(uint32_t* r, uint32_t addr) {
    asm volatile("ldmatrix.sync.aligned.m8n8.x4.shared.b16 {%0,%1,%2,%3}, [%4];"
                 : "=r"(r[0]), "=r"(r[1]), "=r"(r[2]), "=r"(r[3]) : "r"(addr));
}
__device__ __forceinline__ void mma16816(float* d, const uint32_t* a, const uint32_t* b) {
    asm volatile(
        "mma.sync.aligned.m16n8k16.row.col.f32.f16.f16.f32 "
        "{%0,%1,%2,%3}, {%4,%5,%6,%7}, {%8,%9}, {%0,%1,%2,%3};"
        : "+f"(d[0]), "+f"(d[1]), "+f"(d[2]), "+f"(d[3])
        : "r"(a[0]), "r"(a[1]), "r"(a[2]), "r"(a[3]), "r"(b[0]), "r"(b[1]));
}

#define MBAR_INIT(a, c) \
    asm volatile("mbarrier.init.shared.b64 [%0], %1;" :: "r"(a), "r"(c) : "memory")
#define MBAR_EXPECT_TX(a, bytes) \
    asm volatile("mbarrier.arrive.expect_tx.shared.b64 _, [%0], %1;" :: "r"(a), "r"(bytes) : "memory")
#define MBAR_WAIT(mb, par) do {                                                        \
    uint32_t _m = (mb), _p = (par), _d;                                                \
    asm volatile("{\n\t.reg .pred p;\n\t"                                              \
        "mbarrier.try_wait.parity.acquire.cta.shared::cta.b64 p, [%1], %2;\n\t"        \
        "selp.b32 %0, 1, 0, p;\n\t}" : "=r"(_d) : "r"(_m), "r"(_p) : "memory");        \
    if (!_d) {                                                                         \
        asm volatile("{\n\t.reg .pred P1;\n\t"                                         \
            "WAIT_LOOP_%=:\n\t"                                                        \
            "mbarrier.try_wait.parity.acquire.cta.shared::cta.b64 P1, [%0], %1, 0x989680;\n\t" \
            "@P1 bra.uni WAIT_DONE_%=;\n\t"                                            \
            "bra.uni WAIT_LOOP_%=;\n\t"                                                \
            "WAIT_DONE_%=:\n\t}" :: "r"(_m), "r"(_p) : "memory");                      \
    }                                                                                  \
} while (0)

// segment bounds (reference semantics)
__device__ __forceinline__ void seg_bounds(int b, int s, int& t0, int& t1) {
    const int n = g_nsep[b];
    t0 = 0; t1 = 0;
    if (n == 0) {
        if (s == 0) { t0 = 0; t1 = SS; }
    } else if (s < n) {
        if (s == 0) { t0 = 0; t1 = g_sep_pos[b][0] + 1; }
        else        { t0 = g_sep_pos[b][s - 1] + 1; t1 = g_sep_pos[b][s]; }
    } else if (s == n) {
        t0 = g_sep_pos[b][n - 1] + 1; t1 = SS - 1;
    }
}

// ---------------- 1) sep scan (shuffle block scan) --------------------------
__global__ void sep_scan_kernel(const int* __restrict__ ids32) {
    const int b = blockIdx.x;
    const int tid = threadIdx.x;                  // 256
    const int stride = (ids32[1] == 0) ? 2 : 1;   // int64 vs int32 auto-detect
    const int* row = ids32 + (size_t)b * SS * stride;

    const int base = tid * 16;
    int c = 0;
    #pragma unroll
    for (int i = 0; i < 16; i++)
        if (row[(base + i) * stride] == SEPTOK) c++;

    const int lane = tid & 31, w = tid >> 5;
    int incl = c;
    #pragma unroll
    for (int o = 1; o < 32; o <<= 1) {
        int t = __shfl_up_sync(0xffffffffu, incl, o);
        if (lane >= o) incl += t;
    }
    __shared__ int wsum[8], woff[8];
    if (lane == 31) wsum[w] = incl;
    __syncthreads();
    if (tid == 0) {
        int a = 0;
        #pragma unroll
        for (int i = 0; i < 8; i++) { woff[i] = a; a += wsum[i]; }
        g_nsep[b] = a;
    }
    __syncthreads();

    int off = woff[w] + incl - c;
    for (int i = 0; i < 16; i++)
        if (row[(base + i) * stride] == SEPTOK)
            g_sep_pos[b][off++] = base + i;
}

// ---------------- 2) pooling via cp.async.bulk (TMA path) -------------------
// Segment tokens are contiguous in hidden[b, t0:t1, :]; stream 48KB chunks
// into a 2-deep smem ring via 1D bulk copies, reduce from smem (LDS crossbar
// 128 B/cyc/SM >> the 16 B/cyc/SM LDG-issue ceiling that capped the old pool).
__global__ void pool_kernel(const float* __restrict__ hidden) {
    const int s   = blockIdx.x;   // 0..63
    const int b   = blockIdx.y;   // 0..7
    const int tid = threadIdx.x;  // 192 (= HH/4)

    extern __shared__ __align__(16) char psm[];       // 2 x CHUNK_BYTES
    __shared__ __align__(8) uint64_t mbar[2];

    int t0, t1;
    seg_bounds(b, s, t0, t1);
    const int len = t1 - t0;
    const int nc  = (len + CHUNK_T - 1) / CHUNK_T;

    const uint32_t smBase = smem_u32(psm);
    const uint32_t mb     = smem_u32(&mbar[0]);

    if (tid == 0) { MBAR_INIT(mb, 1); MBAR_INIT(mb + 8, 1); }
    __syncthreads();

    const float* src0 = hidden + (size_t)b * SS * HH + (size_t)t0 * HH;

    auto issue = [&](int i) {   // tid==0 only
        const int ct = min(CHUNK_T, len - i * CHUNK_T);
        const uint32_t bytes = (uint32_t)ct * HH * 4;
        const uint32_t mbi = mb + (uint32_t)((i & 1) * 8);
        MBAR_EXPECT_TX(mbi, bytes);
        asm volatile(
            "cp.async.bulk.shared::cluster.global.mbarrier::complete_tx::bytes "
            "[%0], [%1], %2, [%3];"
            :: "r"(smBase + (uint32_t)((i & 1) * CHUNK_BYTES)),
               "l"(src0 + (size_t)i * CHUNK_T * HH), "r"(bytes), "r"(mbi)
            : "memory");
    };

    if (tid == 0) {
        if (nc > 0) issue(0);
        if (nc > 1) issue(1);
    }

    float4 acc = make_float4(0.f, 0.f, 0.f, 0.f);
    for (int i = 0; i < nc; i++) {
        MBAR_WAIT(mb + (i & 1) * 8, (i >> 1) & 1);
        const int ct = min(CHUNK_T, len - i * CHUNK_T);
        const float4* buf = (const float4*)(psm + (i & 1) * CHUNK_BYTES);
        for (int t = 0; t < ct; t++) {
            float4 v = buf[t * 192 + tid];
            acc.x += v.x; acc.y += v.y; acc.z += v.z; acc.w += v.w;
        }
        __syncthreads();                       // buffer (i&1) free for reuse
        if (tid == 0 && i + 2 < nc) issue(i + 2);
    }

    const float inv = (len > 0) ? (1.0f / (float)len) : 0.0f;
    const size_t rb = (size_t)(b * MS + s) * HH + tid * 4;
    *(__half2*)(&g_sentb[rb]) =
        __halves2half2(__float2half(acc.x * inv), __float2half(acc.y * inv));
    *(__half2*)(&g_sentb[rb + 2]) =
        __halves2half2(__float2half(acc.z * inv), __float2half(acc.w * inv));
}

// ---------------- 3) weight transpose, fp16 -------------------------------
// W: [K, N] row-major  ->  out: [N, K] fp16
__global__ void conv_w_kernel(const float* __restrict__ W, __half* __restrict__ out,
                              int K, int N) {
    __shared__ float t[32][33];
    const int n0 = blockIdx.x * 32, k0 = blockIdx.y * 32;
    const int tx = threadIdx.x, ty = threadIdx.y;   // 32 x 8
    #pragma unroll
    for (int i = 0; i < 4; i++)
        t[ty + i * 8][tx] = W[(size_t)(k0 + ty + i * 8) * N + n0 + tx];
    __syncthreads();
    #pragma unroll
    for (int i = 0; i < 4; i++) {
        const int nn = n0 + ty + i * 8;
        out[(size_t)nn * K + k0 + tx] = __float2half(t[tx][ty + i * 8]);
    }
}

// ---------------- 4) mma.sync fp16 GEMM, 128x128 tile, K staged 128 ---------
// A: [M, lda] K-major fp16.  B: [N, ldb] K-major fp16 (B^T).
// 3-deep cp.async ring; 8 warps 4(m)x2(n), warp tile 32x64.
// EPI==1: D + bias -> GELU -> fp16 x1.  EPI==0: fp32 split-K partials.
template<int EPI>
__global__ __launch_bounds__(256)
void mma_gemm(const __half* __restrict__ A, int lda,
              const __half* __restrict__ Bm, int ldb,
              int nStages,            // number of 128-wide K stages
              const float* __restrict__ bias,
              float* __restrict__ Cout,
              __half* __restrict__ OutB)
{
    extern __shared__ char dsm_raw[];
    char* dsm = (char*)(((uintptr_t)dsm_raw + 1023) & ~(uintptr_t)1023);

    const int tid  = threadIdx.x;
    const int wid  = tid >> 5, lane = tid & 31;
    const int m0   = blockIdx.y * 128;
    const int n0   = blockIdx.x * 128;
    const int z    = blockIdx.z;
    const int ks0  = z * nStages * 128;

    const uint32_t smBase = smem_u32(dsm);

    auto load_stage = [&](int buf, int s) {
        const int ko = ks0 + s * 128;
        const uint32_t dA = smBase + buf * 32768;
        const uint32_t dB = smBase + 98304 + buf * 32768;
        #pragma unroll
        for (int sub = 0; sub < 2; sub++) {
            const __half* Ag = A  + (size_t)m0 * lda + ko + sub * 64;
            const __half* Bg = Bm + (size_t)n0 * ldb + ko + sub * 64;
            #pragma unroll
            for (int i = 0; i < 4; i++) {
                const int ch = tid + i * 256;     // 1024 16B chunks / sub-tile
                const int r = ch >> 3, c = ch & 7;
                const uint32_t sw = sw128((uint32_t)(r * 128 + c * 16)) + sub * 16384;
                cp_async16(dA + sw, Ag + (size_t)r * lda + c * 8);
                cp_async16(dB + sw, Bg + (size_t)r * ldb + c * 8);
            }
        }
    };

    // ---- warp/lane fragment geometry
    const int wm0 = (wid & 3) * 32;
    const int wn0 = (wid >> 2) * 64;
    const int grp = lane >> 3, rowin = lane & 7;
    const int a_mloc = rowin + ((grp & 1) << 3);
    const int a_koff = (grp >> 1) << 4;
    const int b_nloc = rowin + ((grp >> 1) << 3);
    const int b_koff = (grp & 1) << 4;

    float acc[2][8][4];
    #pragma unroll
    for (int mt = 0; mt < 2; mt++)
        #pragma unroll
        for (int nt = 0; nt < 8; nt++)
            #pragma unroll
            for (int q = 0; q < 4; q++) acc[mt][nt][q] = 0.f;

    load_stage(0, 0);
    cp_commit();
    if (nStages > 1) { load_stage(1, 1); cp_commit(); }

    int buf = 0;
    for (int s = 0; s < nStages; s++) {
        if (s + 1 < nStages) cp_waitg<1>(); else cp_waitg<0>();
        __syncthreads();

        #pragma unroll
        for (int sub = 0; sub < 2; sub++) {
            const uint32_t uA = smBase + buf * 32768 + sub * 16384;
            const uint32_t uB = smBase + 98304 + buf * 32768 + sub * 16384;
            const uint32_t aRow[2] = {
                uA + (uint32_t)((wm0 + a_mloc) * 128),
                uA + (uint32_t)((wm0 + 16 + a_mloc) * 128) };
            const uint32_t aXor = (uint32_t)(((wm0 + a_mloc) & 7) << 4);
            const uint32_t bXor = (uint32_t)(((wn0 + b_nloc) & 7) << 4);

            #pragma unroll
            for (int kk = 0; kk < 4; kk++) {
                uint32_t afr[2][4];
                #pragma unroll
                for (int mt = 0; mt < 2; mt++)
                    ldsm_x4(afr[mt], aRow[mt] + (((uint32_t)(kk * 32 + a_koff)) ^ aXor));

                uint32_t bfr[8][2];
                #pragma unroll
                for (int p = 0; p < 4; p++) {
                    uint32_t r4[4];
                    const uint32_t bRow = uB + (uint32_t)((wn0 + p * 16 + b_nloc) * 128);
                    ldsm_x4(r4, bRow + (((uint32_t)(kk * 32 + b_koff)) ^ bXor));
                    bfr[2 * p][0] = r4[0]; bfr[2 * p][1] = r4[1];
                    bfr[2 * p + 1][0] = r4[2]; bfr[2 * p + 1][1] = r4[3];
                }

                #pragma unroll
                for (int mt = 0; mt < 2; mt++)
                    #pragma unroll
                    for (int nt = 0; nt < 8; nt++)
                        mma16816(acc[mt][nt], afr[mt], bfr[nt]);
            }
        }

        // 3-buffer ring: overwrite target was consumed at stage s-1; the
        // top-of-loop barrier for stage s already fenced all its readers.
        if (s + 2 < nStages) { load_stage((s + 2) % 3, s + 2); cp_commit(); }
        buf = (buf + 1) % 3;
    }

    // ---- epilogue
    #pragma unroll
    for (int mt = 0; mt < 2; mt++) {
        const int rA = m0 + wm0 + mt * 16 + (lane >> 2);
        #pragma unroll
        for (int half = 0; half < 2; half++) {
            const int r = rA + half * 8;
            if (EPI == 1) {
                const size_t rowbase = (size_t)r * F1;
                #pragma unroll
                for (int nt = 0; nt < 8; nt++) {
                    const int f = n0 + wn0 + nt * 8 + (lane & 3) * 2;
                    float v0 = gelu_exact(acc[mt][nt][2 * half]     + __ldg(&bias[f]));
                    float v1 = gelu_exact(acc[mt][nt][2 * half + 1] + __ldg(&bias[f + 1]));
                    *(__half2*)(&OutB[rowbase + f]) =
                        __halves2half2(__float2half(v0), __float2half(v1));
                }
            } else {
                float* Cp = Cout + (size_t)z * MROWS * F2 + (size_t)r * F2;
                #pragma unroll
                for (int nt = 0; nt < 8; nt++) {
                    const int f = n0 + wn0 + nt * 8 + (lane & 3) * 2;
                    float2 v; v.x = acc[mt][nt][2 * half]; v.y = acc[mt][nt][2 * half + 1];
                    *(float2*)(Cp + f) = v;
                }
            }
        }
    }
}

// ---------------- 5) fused split-K reduce + bias + GELU + head --------------
__global__ void reduce_head_kernel(const float* __restrict__ b2,
                                   const float* __restrict__ W3,
                                   const float* __restrict__ b3,
                                   float* __restrict__ out) {
    const int row = blockIdx.x;   // 512
    const int tid = threadIdx.x;  // 256
    const int idx = row * F2 + tid;
    float s = 0.f;
    #pragma unroll
    for (int i = 0; i < NSPLIT; i++) s += g_x2p[(size_t)i * MROWS * F2 + idx];
    const float x = gelu_exact(s + b2[tid]);

    __shared__ float sh0[256];
    __shared__ float sh1[256];
    sh0[tid] = x * W3[tid * 2 + 0];
    sh1[tid] = x * W3[tid * 2 + 1];
    __syncthreads();
    for (int o = 128; o > 0; o >>= 1) {
        if (tid < o) { sh0[tid] += sh0[tid + o]; sh1[tid] += sh1[tid + o]; }
        __syncthreads();
    }
    if (tid == 0) {
        out[row * 2 + 0] = sh0[0] + b3[0];
        out[row * 2 + 1] = sh1[0] + b3[1];
    }
}

// ---------------- launch ----------------------------------------------------
extern "C" void kernel_launch(void* const* d_in, const int* in_sizes, int n_in,
                              void* d_out, int out_size) {
    const float* hidden = (const float*)d_in[0];
    const int*   ids32  = (const int*)  d_in[1];
    const float* W1 = (const float*)d_in[2];
    const float* b1 = (const float*)d_in[3];
    const float* W2 = (const float*)d_in[4];
    const float* b2 = (const float*)d_in[5];
    const float* W3 = (const float*)d_in[6];
    const float* b3 = (const float*)d_in[7];
    float* out = (float*)d_out;

    void *p_sentb, *p_w1b, *p_x1b, *p_w2b, *p_x2p;
    cudaGetSymbolAddress(&p_sentb, g_sentb);
    cudaGetSymbolAddress(&p_w1b,   g_w1b);
    cudaGetSymbolAddress(&p_x1b,   g_x1b);
    cudaGetSymbolAddress(&p_w2b,   g_w2b);
    cudaGetSymbolAddress(&p_x2p,   g_x2p);

    // lazily created host-side objects (no device memory involved); the
    // enqueued work graph is identical on every call.
    static cudaStream_t s1 = nullptr;
    static cudaEvent_t eFork = nullptr, eJoin = nullptr;
    if (s1 == nullptr) {
        cudaStreamCreateWithFlags(&s1, cudaStreamNonBlocking);
        cudaEventCreateWithFlags(&eFork, cudaEventDisableTiming);
        cudaEventCreateWithFlags(&eJoin, cudaEventDisableTiming);
    }

    const int SMEM_DYN = 197632;          // GEMM: 3 x (32KB A + 32KB B) + slack
    const int SMEM_POOL = 2 * CHUNK_BYTES;
    cudaFuncSetAttribute(mma_gemm<1>, cudaFuncAttributeMaxDynamicSharedMemorySize, SMEM_DYN);
    cudaFuncSetAttribute(mma_gemm<0>, cudaFuncAttributeMaxDynamicSharedMemorySize, SMEM_DYN);
    cudaFuncSetAttribute(pool_kernel, cudaFuncAttributeMaxDynamicSharedMemorySize, SMEM_POOL);

    // fork: weight conversions run on s1 concurrently with sep+pool
    cudaEventRecord(eFork, 0);
    cudaStreamWaitEvent(s1, eFork, 0);
    conv_w_kernel<<<dim3(F1 / 32, HH / 32), dim3(32, 8), 0, s1>>>(
        W1, (__half*)p_w1b, HH, F1);
    conv_w_kernel<<<dim3(F2 / 32, F1 / 32), dim3(32, 8), 0, s1>>>(
        W2, (__half*)p_w2b, F1, F2);
    cudaEventRecord(eJoin, s1);

    sep_scan_kernel<<<BB, 256>>>(ids32);
    pool_kernel<<<dim3(MS, BB), 192, SMEM_POOL>>>(hidden);

    // join before GEMM1 (covers GEMM2's W2 dependency as well)
    cudaStreamWaitEvent(0, eJoin, 0);

    // GEMM1: [512, 768] x [4096, 768]^T -> gelu -> fp16 x1  (6 stages)
    mma_gemm<1><<<dim3(F1 / 128, MROWS / 128, 1), 256, SMEM_DYN>>>(
        (const __half*)p_sentb, HH, (const __half*)p_w1b, HH,
        HH / 128, b1, nullptr, (__half*)p_x1b);

    // GEMM2: [512, 4096] x [256, 4096]^T, split-K=16 -> fp32 partials (2 stages)
    mma_gemm<0><<<dim3(F2 / 128, MROWS / 128, NSPLIT), 256, SMEM_DYN>>>(
        (const __half*)p_x1b, F1, (const __half*)p_w2b, F1,
        F1 / (128 * NSPLIT), nullptr, (float*)p_x2p, nullptr);

    reduce_head_kernel<<<MROWS, 256>>>(b2, W3, b3, out);
}